// round 9
// baseline (speedup 1.0000x reference)
#include <cuda_runtime.h>

#define NPTS  4096
#define NB    8
#define CDIM  32
#define KOUT  9
#define KALL  18
#define TILE  128
#define NTHREADS 512

// shared memory layout (float offsets)
#define SM_QT 0
#define SM_PT (SM_QT + CDIM*TILE)          // 4096
#define SM_RN (SM_PT + CDIM*TILE)          // 8192
#define SM_CN (SM_RN + TILE)               // 8320
#define SM_TH (SM_CN + TILE)               // 8448 row thresholds
#define SM_CT (SM_TH + TILE)               // 8576 survivor counts (int)
#define SM_SD (SM_CT + TILE)               // 8704 survivor dists 128x128
#define SM_SI (SM_SD + TILE*TILE)          // 25088 survivor idx (short) 128x128
#define SMEM_FLOATS (SM_SI + (TILE*TILE)/2)
#define SMEM_BYTES  (SMEM_FLOATS * 4)      // 108,544 bytes

__device__ float g_sq[NB * NPTS];

__global__ void sqnorm_kernel(const float* __restrict__ x) {
    int idx = blockIdx.x * blockDim.x + threadIdx.x;
    if (idx >= NB * NPTS) return;
    int b = idx >> 12;
    int n = idx & (NPTS - 1);
    const float* p = x + (size_t)(b * CDIM) * NPTS + n;
    float s = 0.f;
#pragma unroll
    for (int c = 0; c < CDIM; c++) {
        float v = p[c * NPTS];
        s = fmaf(v, v, s);
    }
    g_sq[idx] = s;
}

// lexicographic (d, idx) less-than: matches jax top_k order (ascending dist,
// lower index first on ties)
#define LEX_LT(d1, i1, d2, i2) ((d1) < (d2) || ((d1) == (d2) && (i1) < (i2)))

// ---------------------------------------------------------------------------
// 128x128 tiles, 512 threads, filter-then-select:
//  - compute: 32x16 grid, 4x8 fragments; distances stay in registers
//  - filter: d <= thr[row] (true row 18th, conservative-stale) -> atomic push
//    of (d, idx) into per-row survivor buffer; ~116 survivors/row total
//  - select: owner thread per row (tid<128) inserts survivors into a
//    register-resident sorted top-18 with lexicographic compares, then
//    updates thr[row]. Output written directly from owner registers.
// ---------------------------------------------------------------------------
__global__ __launch_bounds__(NTHREADS, 1)
void knn_kernel(const float* __restrict__ x, float* __restrict__ out) {
    extern __shared__ float sm[];
    float* qt   = sm + SM_QT;
    float* pt   = sm + SM_PT;
    float* rn   = sm + SM_RN;
    float* cn   = sm + SM_CN;
    float* thr_s = sm + SM_TH;
    int*   scnt = (int*)(sm + SM_CT);
    float* sdist = sm + SM_SD;
    short* sidx  = (short*)(sm + SM_SI);

    const int b    = blockIdx.y;
    const int row0 = blockIdx.x * TILE;
    const int tid  = threadIdx.x;
    const int tx   = tid & 15;          // 16 column-groups
    const int ty   = tid >> 4;          // 32 row-groups (rows 4ty..4ty+3)
    const float* xb = x + (size_t)(b * CDIM) * NPTS;

    // owner state: sorted top-18 for row `tid` (tid < 128)
    float dl[KALL];
    int   il[KALL];
#pragma unroll
    for (int j = 0; j < KALL; j++) { dl[j] = 3.4e38f; il[j] = 0x7FFFFFFF; }

    // query tile + init
#pragma unroll
    for (int k = 0; k < (CDIM * TILE) / NTHREADS; k++) {
        int idx = k * NTHREADS + tid;
        qt[idx] = xb[(idx >> 7) * NPTS + row0 + (idx & 127)];
    }
    if (tid < TILE) {
        rn[tid] = g_sq[b * NPTS + row0 + tid];
        thr_s[tid] = 3.4e38f;
    }
    __syncthreads();

    for (int m0 = 0; m0 < NPTS; m0 += TILE) {
        // candidate tile + per-tile reset
#pragma unroll
        for (int k = 0; k < (CDIM * TILE) / NTHREADS; k++) {
            int idx = k * NTHREADS + tid;
            pt[idx] = xb[(idx >> 7) * NPTS + m0 + (idx & 127)];
        }
        if (tid < TILE) {
            cn[tid] = g_sq[b * NPTS + m0 + tid];
            scnt[tid] = 0;
        }
        __syncthreads();

        // ---- 128x128x32 inner products, 4x8 per thread ----
        float acc[4][8];
#pragma unroll
        for (int i = 0; i < 4; i++)
#pragma unroll
            for (int j = 0; j < 8; j++) acc[i][j] = 0.f;

#pragma unroll 2
        for (int c = 0; c < CDIM; c++) {
            float4 q  = *(const float4*)(qt + c * TILE + 4 * ty);
            float4 pa = *(const float4*)(pt + c * TILE + 4 * tx);
            float4 pb = *(const float4*)(pt + c * TILE + 64 + 4 * tx);
            float qv[4] = {q.x, q.y, q.z, q.w};
            float pv[8] = {pa.x, pa.y, pa.z, pa.w, pb.x, pb.y, pb.z, pb.w};
#pragma unroll
            for (int i = 0; i < 4; i++)
#pragma unroll
                for (int j = 0; j < 8; j++)
                    acc[i][j] = fmaf(qv[i], pv[j], acc[i][j]);
        }

        // ---- fused epilogue + filter: push survivors to per-row buffers ----
        float cnv[8];
#pragma unroll
        for (int j = 0; j < 8; j++)
            cnv[j] = cn[(j < 4) ? (4 * tx + j) : (60 + 4 * tx + j)];

#pragma unroll
        for (int i = 0; i < 4; i++) {
            int r = 4 * ty + i;
            float rni = rn[r];
            float tv  = thr_s[r];
#pragma unroll
            for (int j = 0; j < 8; j++) {
                float d = (rni - 2.f * acc[i][j]) + cnv[j];
                if (d <= tv) {   // <= : keep equal-dist candidates (index ties)
                    int jc = (j < 4) ? (4 * tx + j) : (60 + 4 * tx + j);
                    int p = atomicAdd(&scnt[r], 1);
                    sdist[r * TILE + p] = d;
                    sidx[r * TILE + p]  = (short)(m0 + jc);
                }
            }
        }
        __syncthreads();

        // ---- owner select: insert survivors into register top-18 ----
        if (tid < TILE) {
            int c = scnt[tid];
            const float* sdr = sdist + tid * TILE;
            const short* sir = sidx + tid * TILE;
            for (int s = 0; s < c; s++) {
                float d  = sdr[s];
                int   mi = (int)sir[s];
                if (LEX_LT(d, mi, dl[KALL - 1], il[KALL - 1])) {
#pragma unroll
                    for (int j = KALL - 1; j >= 1; j--) {
                        bool sh = LEX_LT(d, mi, dl[j - 1], il[j - 1]);
                        bool pl = !sh && LEX_LT(d, mi, dl[j], il[j]);
                        float pd = dl[j - 1]; int pi = il[j - 1];
                        dl[j] = sh ? pd : (pl ? d  : dl[j]);
                        il[j] = sh ? pi : (pl ? mi : il[j]);
                    }
                    if (LEX_LT(d, mi, dl[0], il[0])) { dl[0] = d; il[0] = mi; }
                }
            }
            thr_s[tid] = dl[KALL - 1];
        }
        __syncthreads();
    }

    // ---- output (float32) straight from owner registers ----
    if (tid < TILE) {
        int n = row0 + tid;
        int base0 = (b * NPTS + n) * KOUT;
        int base1 = ((NB + b) * NPTS + n) * KOUT;
#pragma unroll
        for (int j = 0; j < KOUT; j++) {
            out[base0 + j] = (float)il[2 * j];
            out[base1 + j] = (float)n;
        }
    }
}

extern "C" void kernel_launch(void* const* d_in, const int* in_sizes, int n_in,
                              void* d_out, int out_size) {
    const float* x = (const float*)d_in[0];
    float* out = (float*)d_out;

    cudaFuncSetAttribute(knn_kernel, cudaFuncAttributeMaxDynamicSharedMemorySize,
                         SMEM_BYTES);

    sqnorm_kernel<<<(NB * NPTS + 511) / 512, 512>>>(x);

    dim3 grid(NPTS / TILE, NB);
    knn_kernel<<<grid, NTHREADS, SMEM_BYTES>>>(x, out);
}

// round 10
// speedup vs baseline: 1.2223x; 1.2223x over previous
#include <cuda_runtime.h>

#define NPTS  4096
#define NB    8
#define CDIM  32
#define KOUT  9
#define KALL  18
#define TILE  128
#define NTHREADS 512

// shared memory layout (float offsets)
#define SM_QT 0
#define SM_PT (SM_QT + CDIM*TILE)          // 4096
#define SM_DT (SM_PT + CDIM*TILE)          // 8192
#define SM_RN (SM_DT + TILE*TILE)          // 24576
#define SM_CN (SM_RN + TILE)               // 24704
#define SM_QH (SM_CN + TILE)               // 24832 quarter thresholds (512)
#define SMEM_FLOATS (SM_QH + NTHREADS)     // 25344
#define SMEM_BYTES  (SMEM_FLOATS * 4)      // 101,376 bytes

__device__ float g_sq[NB * NPTS];

__global__ void sqnorm_kernel(const float* __restrict__ x) {
    int idx = blockIdx.x * blockDim.x + threadIdx.x;
    if (idx >= NB * NPTS) return;
    int b = idx >> 12;
    int n = idx & (NPTS - 1);
    const float* p = x + (size_t)(b * CDIM) * NPTS + n;
    float s = 0.f;
#pragma unroll
    for (int c = 0; c < CDIM; c++) {
        float v = p[c * NPTS];
        s = fmaf(v, v, s);
    }
    g_sq[idx] = s;
}

// ---------------------------------------------------------------------------
// 128x128 tiles, 512 threads (R8 skeleton):
//  - compute: 32x16 thread grid, 4x8 fragments (32 indep FMA chains)
//  - scan: thread owns a quarter-row (row = tid>>2), register top-18 via
//    branch-free predicated shifts
//  - NEW: insert guard uses the ROW-shared bound = min over the row's 4
//    quarter-18ths (valid upper bound on the final row-18th), published to
//    smem each tile -> ~4x fewer network executions
//  - end: 4-way lexicographic (d, idx) merge per row == jax top_k order
// ---------------------------------------------------------------------------
__global__ __launch_bounds__(NTHREADS, 1)
void knn_kernel(const float* __restrict__ x, float* __restrict__ out) {
    extern __shared__ float sm[];
    float* qt = sm + SM_QT;
    float* pt = sm + SM_PT;
    float* dt = sm + SM_DT;   // 128x128, chunk-swizzled; reused for merge
    float* rn = sm + SM_RN;
    float* cn = sm + SM_CN;
    float* qh = sm + SM_QH;   // per-quarter-thread current 18th

    const int b    = blockIdx.y;
    const int row0 = blockIdx.x * TILE;
    const int tid  = threadIdx.x;
    const int tx   = tid & 15;
    const int ty   = tid >> 4;
    const float* xb = x + (size_t)(b * CDIM) * NPTS;

    const int srow = tid >> 2;          // scan row
    const int sq   = tid & 3;           // scan quarter
    const int ssw  = srow & 31;

    float dl[KALL];
    int   il[KALL];
#pragma unroll
    for (int j = 0; j < KALL; j++) { dl[j] = 3.4e38f; il[j] = 0x7FFFFFFF; }

#pragma unroll
    for (int k = 0; k < (CDIM * TILE) / NTHREADS; k++) {
        int idx = k * NTHREADS + tid;
        qt[idx] = xb[(idx >> 7) * NPTS + row0 + (idx & 127)];
    }
    if (tid < TILE) rn[tid] = g_sq[b * NPTS + row0 + tid];
    qh[tid] = 3.4e38f;
    __syncthreads();

    for (int m0 = 0; m0 < NPTS; m0 += TILE) {
        // candidate tile
#pragma unroll
        for (int k = 0; k < (CDIM * TILE) / NTHREADS; k++) {
            int idx = k * NTHREADS + tid;
            pt[idx] = xb[(idx >> 7) * NPTS + m0 + (idx & 127)];
        }
        if (tid < TILE) cn[tid] = g_sq[b * NPTS + m0 + tid];
        __syncthreads();

        // ---- 128x128x32 inner products, 4x8 per thread ----
        float acc[4][8];
#pragma unroll
        for (int i = 0; i < 4; i++)
#pragma unroll
            for (int j = 0; j < 8; j++) acc[i][j] = 0.f;

#pragma unroll 2
        for (int c = 0; c < CDIM; c++) {
            float4 q  = *(const float4*)(qt + c * TILE + 4 * ty);
            float4 pa = *(const float4*)(pt + c * TILE + 4 * tx);
            float4 pb = *(const float4*)(pt + c * TILE + 64 + 4 * tx);
            float qv[4] = {q.x, q.y, q.z, q.w};
            float pv[8] = {pa.x, pa.y, pa.z, pa.w, pb.x, pb.y, pb.z, pb.w};
#pragma unroll
            for (int i = 0; i < 4; i++)
#pragma unroll
                for (int j = 0; j < 8; j++)
                    acc[i][j] = fmaf(qv[i], pv[j], acc[i][j]);
        }

        // ---- epilogue: d = (rn - 2*acc) + cn, swizzled float4 stores ----
        float cnv[8];
#pragma unroll
        for (int j = 0; j < 8; j++)
            cnv[j] = cn[(j < 4) ? (4 * tx + j) : (60 + 4 * tx + j)];

#pragma unroll
        for (int i = 0; i < 4; i++) {
            int r = 4 * ty + i;
            float rni = rn[r];
            float4 v0, v1;
            v0.x = (rni - 2.f * acc[i][0]) + cnv[0];
            v0.y = (rni - 2.f * acc[i][1]) + cnv[1];
            v0.z = (rni - 2.f * acc[i][2]) + cnv[2];
            v0.w = (rni - 2.f * acc[i][3]) + cnv[3];
            v1.x = (rni - 2.f * acc[i][4]) + cnv[4];
            v1.y = (rni - 2.f * acc[i][5]) + cnv[5];
            v1.z = (rni - 2.f * acc[i][6]) + cnv[6];
            v1.w = (rni - 2.f * acc[i][7]) + cnv[7];
            int sw = r & 31;
            float4* dtr = (float4*)dt + r * 32;
            dtr[tx ^ sw]        = v0;
            dtr[(16 + tx) ^ sw] = v1;
        }
        __syncthreads();

        // ---- quarter-row scan with ROW-shared threshold ----
        {
            // row bound = min of the 4 quarter-18ths (includes own)
            const float* qhr = qh + srow * 4;
            float tv = fminf(fminf(qhr[0], qhr[1]), fminf(qhr[2], qhr[3]));

            const float4* dtr = (const float4*)dt + srow * 32;
#pragma unroll
            for (int l = 0; l < 8; l++) {
                float4 v = dtr[(sq * 8 + l) ^ ssw];
                int mb = m0 + sq * 32 + 4 * l;
                float dv[4] = {v.x, v.y, v.z, v.w};
#pragma unroll
                for (int e = 0; e < 4; e++) {
                    float d = dv[e];
                    if (d <= tv) {   // <= keeps boundary/index-tie candidates
                        int mi = mb + e;
                        // branch-free sorted insert (ascending m per quarter
                        // -> equal d lands after, preserving lower-index-first)
#pragma unroll
                        for (int j = KALL - 1; j >= 1; j--) {
                            bool sh = d < dl[j - 1];
                            bool pl = !sh && (d < dl[j]);
                            float pd = dl[j - 1]; int pi = il[j - 1];
                            dl[j] = sh ? pd : (pl ? d  : dl[j]);
                            il[j] = sh ? pi : (pl ? mi : il[j]);
                        }
                        if (d < dl[0]) { dl[0] = d; il[0] = mi; }
                    }
                }
            }
            qh[tid] = dl[KALL - 1];   // publish for next tile
        }
        __syncthreads();
    }

    // ---- dump quarter lists into dt region, then 4-way merge per row ----
    float* sd = dt;                       // 512*18 floats
    short* si = (short*)(dt + NTHREADS * KALL);
#pragma unroll
    for (int j = 0; j < KALL; j++) {
        sd[tid * KALL + j] = dl[j];
        si[tid * KALL + j] = (short)il[j];
    }
    __syncthreads();

    if (tid < TILE) {
        int cur[4] = {0, 0, 0, 0};
        int n = row0 + tid;
        int base0 = (b * NPTS + n) * KOUT;
        int base1 = ((NB + b) * NPTS + n) * KOUT;
#pragma unroll
        for (int t = 0; t < KALL; t++) {
            float bd = 3.5e38f;
            int   bi = 0x7FFFFFFF;
            int   bq = 0;
#pragma unroll
            for (int q = 0; q < 4; q++) {
                int c = cur[q];
                float d2 = sd[(tid * 4 + q) * KALL + c];
                int   i2 = (int)si[(tid * 4 + q) * KALL + c];
                if (d2 < bd || (d2 == bd && i2 < bi)) { bd = d2; bi = i2; bq = q; }
            }
            cur[bq]++;
            if ((t & 1) == 0) out[base0 + (t >> 1)] = (float)bi;
        }
#pragma unroll
        for (int j = 0; j < KOUT; j++) out[base1 + j] = (float)n;
    }
}

extern "C" void kernel_launch(void* const* d_in, const int* in_sizes, int n_in,
                              void* d_out, int out_size) {
    const float* x = (const float*)d_in[0];
    float* out = (float*)d_out;

    cudaFuncSetAttribute(knn_kernel, cudaFuncAttributeMaxDynamicSharedMemorySize,
                         SMEM_BYTES);

    sqnorm_kernel<<<(NB * NPTS + 511) / 512, 512>>>(x);

    dim3 grid(NPTS / TILE, NB);
    knn_kernel<<<grid, NTHREADS, SMEM_BYTES>>>(x, out);
}

// round 11
// speedup vs baseline: 1.8799x; 1.5380x over previous
#include <cuda_runtime.h>

#define NPTS  4096
#define NB    8
#define CDIM  32
#define KOUT  9
#define KALL  18
#define TILE  128
#define NTHREADS 512
#define CAP   32

// shared memory layout (float offsets)
#define SM_QT 0
#define SM_PT (SM_QT + CDIM*TILE)          // 4096
#define SM_DT (SM_PT + CDIM*TILE)          // 8192
#define SM_RN (SM_DT + TILE*TILE)          // 24576
#define SM_CN (SM_RN + TILE)               // 24704
#define SM_QH (SM_CN + TILE)               // 24832
#define SM_BD (SM_QH + NTHREADS)           // 25344  survivor dists [CAP][512]
#define SM_BI (SM_BD + CAP*NTHREADS)       // 41728  survivor idx (short) [CAP][512]
#define SMEM_FLOATS (SM_BI + (CAP*NTHREADS)/2)   // 49920
#define SMEM_BYTES  (SMEM_FLOATS * 4)      // 199,680 bytes

__device__ float g_sq[NB * NPTS];

__global__ void sqnorm_kernel(const float* __restrict__ x) {
    int idx = blockIdx.x * blockDim.x + threadIdx.x;
    if (idx >= NB * NPTS) return;
    int b = idx >> 12;
    int n = idx & (NPTS - 1);
    const float* p = x + (size_t)(b * CDIM) * NPTS + n;
    float s = 0.f;
#pragma unroll
    for (int c = 0; c < CDIM; c++) {
        float v = p[c * NPTS];
        s = fmaf(v, v, s);
    }
    g_sq[idx] = s;
}

// ---------------------------------------------------------------------------
// 128x128 tiles, 512 threads (R10 skeleton + batch-deferred insertion):
//  - compute: 32x16 thread grid, 4x8 fragments
//  - scan phase A (filter): d <= row-shared bound -> lane-private smem push
//    (buf[slot][tid] layout: conflict-free STS at any per-lane count)
//  - scan phase B (batch): insert network runs warp-max(cnt) times; inactive
//    lanes carry d=+INF which is a provable no-op through the strict-< net
//  - end: 4-way lexicographic (d, idx) merge per row == jax top_k order
// ---------------------------------------------------------------------------
__global__ __launch_bounds__(NTHREADS, 1)
void knn_kernel(const float* __restrict__ x, float* __restrict__ out) {
    extern __shared__ float sm[];
    float* qt = sm + SM_QT;
    float* pt = sm + SM_PT;
    float* dt = sm + SM_DT;   // 128x128, chunk-swizzled; reused for merge
    float* rn = sm + SM_RN;
    float* cn = sm + SM_CN;
    float* qh = sm + SM_QH;   // per-quarter-thread current 18th
    float* bd = sm + SM_BD;   // survivor dists  [CAP][NTHREADS]
    short* bi = (short*)(sm + SM_BI); // survivor idx [CAP][NTHREADS]

    const int b    = blockIdx.y;
    const int row0 = blockIdx.x * TILE;
    const int tid  = threadIdx.x;
    const int tx   = tid & 15;
    const int ty   = tid >> 4;
    const float* xb = x + (size_t)(b * CDIM) * NPTS;

    const int srow = tid >> 2;          // scan row
    const int sq   = tid & 3;           // scan quarter
    const int ssw  = srow & 31;

    float dl[KALL];
    int   il[KALL];
#pragma unroll
    for (int j = 0; j < KALL; j++) { dl[j] = 3.4e38f; il[j] = 0x7FFFFFFF; }

#pragma unroll
    for (int k = 0; k < (CDIM * TILE) / NTHREADS; k++) {
        int idx = k * NTHREADS + tid;
        qt[idx] = xb[(idx >> 7) * NPTS + row0 + (idx & 127)];
    }
    if (tid < TILE) rn[tid] = g_sq[b * NPTS + row0 + tid];
    qh[tid] = 3.4e38f;
    __syncthreads();

    for (int m0 = 0; m0 < NPTS; m0 += TILE) {
        // candidate tile
#pragma unroll
        for (int k = 0; k < (CDIM * TILE) / NTHREADS; k++) {
            int idx = k * NTHREADS + tid;
            pt[idx] = xb[(idx >> 7) * NPTS + m0 + (idx & 127)];
        }
        if (tid < TILE) cn[tid] = g_sq[b * NPTS + m0 + tid];
        __syncthreads();

        // ---- 128x128x32 inner products, 4x8 per thread ----
        float acc[4][8];
#pragma unroll
        for (int i = 0; i < 4; i++)
#pragma unroll
            for (int j = 0; j < 8; j++) acc[i][j] = 0.f;

#pragma unroll 2
        for (int c = 0; c < CDIM; c++) {
            float4 q  = *(const float4*)(qt + c * TILE + 4 * ty);
            float4 pa = *(const float4*)(pt + c * TILE + 4 * tx);
            float4 pb = *(const float4*)(pt + c * TILE + 64 + 4 * tx);
            float qv[4] = {q.x, q.y, q.z, q.w};
            float pv[8] = {pa.x, pa.y, pa.z, pa.w, pb.x, pb.y, pb.z, pb.w};
#pragma unroll
            for (int i = 0; i < 4; i++)
#pragma unroll
                for (int j = 0; j < 8; j++)
                    acc[i][j] = fmaf(qv[i], pv[j], acc[i][j]);
        }

        // ---- epilogue: d = (rn - 2*acc) + cn, swizzled float4 stores ----
        float cnv[8];
#pragma unroll
        for (int j = 0; j < 8; j++)
            cnv[j] = cn[(j < 4) ? (4 * tx + j) : (60 + 4 * tx + j)];

#pragma unroll
        for (int i = 0; i < 4; i++) {
            int r = 4 * ty + i;
            float rni = rn[r];
            float4 v0, v1;
            v0.x = (rni - 2.f * acc[i][0]) + cnv[0];
            v0.y = (rni - 2.f * acc[i][1]) + cnv[1];
            v0.z = (rni - 2.f * acc[i][2]) + cnv[2];
            v0.w = (rni - 2.f * acc[i][3]) + cnv[3];
            v1.x = (rni - 2.f * acc[i][4]) + cnv[4];
            v1.y = (rni - 2.f * acc[i][5]) + cnv[5];
            v1.z = (rni - 2.f * acc[i][6]) + cnv[6];
            v1.w = (rni - 2.f * acc[i][7]) + cnv[7];
            int sw = r & 31;
            float4* dtr = (float4*)dt + r * 32;
            dtr[tx ^ sw]        = v0;
            dtr[(16 + tx) ^ sw] = v1;
        }
        __syncthreads();

        // ---- phase A: filter quarter-row, push survivors (cheap) ----
        {
            const float* qhr = qh + srow * 4;
            float tv = fminf(fminf(qhr[0], qhr[1]), fminf(qhr[2], qhr[3]));

            const float4* dtr = (const float4*)dt + srow * 32;
            int cnt = 0;
#pragma unroll
            for (int l = 0; l < 8; l++) {
                float4 v = dtr[(sq * 8 + l) ^ ssw];
                int mb = m0 + sq * 32 + 4 * l;
                float dv[4] = {v.x, v.y, v.z, v.w};
#pragma unroll
                for (int e = 0; e < 4; e++) {
                    float d = dv[e];
                    if (d <= tv) {   // <= keeps boundary/index-tie candidates
                        bd[cnt * NTHREADS + tid] = d;
                        bi[cnt * NTHREADS + tid] = (short)(mb + e);
                        cnt++;
                    }
                }
            }

            // ---- phase B: batch insert, warp-max(cnt) network runs ----
            int nmax = __reduce_max_sync(0xFFFFFFFFu, cnt);
            for (int t = 0; t < nmax; t++) {
                float d  = 3.4e38f;
                int   mi = 0x7FFFFFFF;
                if (t < cnt) {
                    d  = bd[t * NTHREADS + tid];
                    mi = (int)bi[t * NTHREADS + tid];
                }
                // branch-free sorted insert; d=+INF lanes are no-ops
                // (ascending m per quarter -> equal d lands after existing,
                //  preserving lower-index-first)
#pragma unroll
                for (int j = KALL - 1; j >= 1; j--) {
                    bool sh = d < dl[j - 1];
                    bool pl = !sh && (d < dl[j]);
                    float pd = dl[j - 1]; int pi = il[j - 1];
                    dl[j] = sh ? pd : (pl ? d  : dl[j]);
                    il[j] = sh ? pi : (pl ? mi : il[j]);
                }
                if (d < dl[0]) { dl[0] = d; il[0] = mi; }
            }
            qh[tid] = dl[KALL - 1];   // publish for next tile
        }
        __syncthreads();
    }

    // ---- dump quarter lists into dt region, then 4-way merge per row ----
    float* sd = dt;                       // 512*18 floats
    short* si = (short*)(dt + NTHREADS * KALL);
#pragma unroll
    for (int j = 0; j < KALL; j++) {
        sd[tid * KALL + j] = dl[j];
        si[tid * KALL + j] = (short)il[j];
    }
    __syncthreads();

    if (tid < TILE) {
        int cur[4] = {0, 0, 0, 0};
        int n = row0 + tid;
        int base0 = (b * NPTS + n) * KOUT;
        int base1 = ((NB + b) * NPTS + n) * KOUT;
#pragma unroll
        for (int t = 0; t < KALL; t++) {
            float bdv = 3.5e38f;
            int   biv = 0x7FFFFFFF;
            int   bq = 0;
#pragma unroll
            for (int q = 0; q < 4; q++) {
                int c = cur[q];
                float d2 = sd[(tid * 4 + q) * KALL + c];
                int   i2 = (int)si[(tid * 4 + q) * KALL + c];
                if (d2 < bdv || (d2 == bdv && i2 < biv)) { bdv = d2; biv = i2; bq = q; }
            }
            cur[bq]++;
            if ((t & 1) == 0) out[base0 + (t >> 1)] = (float)biv;
        }
#pragma unroll
        for (int j = 0; j < KOUT; j++) out[base1 + j] = (float)n;
    }
}

extern "C" void kernel_launch(void* const* d_in, const int* in_sizes, int n_in,
                              void* d_out, int out_size) {
    const float* x = (const float*)d_in[0];
    float* out = (float*)d_out;

    cudaFuncSetAttribute(knn_kernel, cudaFuncAttributeMaxDynamicSharedMemorySize,
                         SMEM_BYTES);

    sqnorm_kernel<<<(NB * NPTS + 511) / 512, 512>>>(x);

    dim3 grid(NPTS / TILE, NB);
    knn_kernel<<<grid, NTHREADS, SMEM_BYTES>>>(x, out);
}